// round 16
// baseline (speedup 1.0000x reference)
#include <cuda_runtime.h>
#include <cuda_fp16.h>
#include <math.h>
#include <stdint.h>

// ---------------- problem constants ----------------
#define BATCH   4
#define SEQLEN  1024
#define BL      4096            // BATCH*SEQLEN
#define DM      512             // D_MODEL
#define DI      1024            // D_INNER
#define DS      64              // D_STATE
#define NH      16              // NHEADS
#define HD      64              // HEADDIM
#define CD      1152            // CONV_DIM = DI + 2*DS
#define DIP     2192            // D_IN_PROJ
#define DIPP    2304            // DIP padded to 256-multiple
#define KC      4               // K_CONV
#define NLAYERS 2

#define NCHUNK  16
#define LCHUNK  (SEQLEN / NCHUNK)   // 64
#define CONV_TT 32                  // time tile for conv kernel

// ---------------- scratch (device globals; no allocation) ----------------
__device__ float g_zx [2][(size_t)BL*DIP];
__device__ float g_xbc[2][(size_t)BL*CD];
__device__ float g_dt [2][BL*NH];
__device__ float g_dA [2][BL*NH];
__device__ float g_y  [2][(size_t)BL*DI];
__device__ float g_tmp[2][(size_t)BL*DM];   // outproj split-K halves
__device__ float g_h  [(size_t)BL*DM];
__device__ float g_state[2][64][NCHUNK][64*64];
__device__ float g_cpv[2][64][SEQLEN];

// fp16 hi/lo split buffers (A side gets hi+lo, weights hi only)
__device__ __half g_ah[2*(size_t)BL*DI];   // GEMM A (activations)
__device__ __half g_al[2*(size_t)BL*DI];
__device__ __half g_ch[(size_t)BL*DI];     // mout output = outproj input
__device__ __half g_cl[(size_t)BL*DI];
__device__ __half g_wi_h[4][(size_t)DIPP*DM];
__device__ __half g_wm_h[4][(size_t)DM*DI];
__device__ __half g_wo_h[(size_t)DM*DI];

// =====================================================================
// low-level helpers
// =====================================================================
__device__ __forceinline__ uint32_t smem_to_u32(const void* p) {
    uint32_t a;
    asm("{ .reg .u64 t; cvta.to.shared.u64 t, %1; cvt.u32.u64 %0, t; }" : "=r"(a) : "l"(p));
    return a;
}
__device__ __forceinline__ void cp16(uint32_t dst, const void* src) {
    asm volatile("cp.async.cg.shared.global [%0], [%1], 16;" :: "r"(dst), "l"(src));
}
#define CP_COMMIT() asm volatile("cp.async.commit_group;" ::: "memory")
template <int N> __device__ __forceinline__ void cp_wait() {
    asm volatile("cp.async.wait_group %0;" :: "n"(N) : "memory");
}
#define LDSM4(R0, R1, R2, R3, addr) \
    asm volatile("ldmatrix.sync.aligned.m8n8.x4.shared.b16 {%0,%1,%2,%3}, [%4];" \
        : "=r"(R0), "=r"(R1), "=r"(R2), "=r"(R3) : "r"(addr))
__device__ __forceinline__ void mma_f16(float* c, const uint32_t* a, const uint32_t* b) {
    asm volatile("mma.sync.aligned.m16n8k16.row.col.f32.f16.f16.f32 "
        "{%0,%1,%2,%3}, {%4,%5,%6,%7}, {%8,%9}, {%0,%1,%2,%3};"
        : "+f"(c[0]), "+f"(c[1]), "+f"(c[2]), "+f"(c[3])
        : "r"(a[0]), "r"(a[1]), "r"(a[2]), "r"(a[3]), "r"(b[0]), "r"(b[1]));
}

#define STAGE_BYTES 65536u     // Ah 16K | Al 16K | Bh 32K
#define GEMM_SMEM   131072     // 2 stages

// scan_pass1 dynamic smem: Xs/Bs/Cs 64 rows x 68 floats each + dts/dAs
#define ROWP        68
#define SCAN_TILE   (64 * ROWP)                 // floats per array
#define SCAN_SMEM   ((3 * SCAN_TILE + 128) * 4) // 53,248 B

// =====================================================================
// HMMA fp16x2 GEMM: C[M,N] = A[M,K]*B[N,K]^T; A split hi/lo, B hi only.
// C = Ah*Bh + Al*Bh  (dropped A*Bl ~ 2^-12 relative).
// CTA tile 128x256, 8 warps (2x4), warp tile 64x64, BK=64, 2 stages.
// =====================================================================
__global__ void __launch_bounds__(256) gemm_tc(
    const __half* __restrict__ Ah, const __half* __restrict__ Al,
    const __half* __restrict__ Bh,
    float* __restrict__ C, __half* __restrict__ Chi, __half* __restrict__ Clo,
    int N, int K, int lda, int ldb, int ldc,
    size_t aS, size_t bS, size_t cS, int mode)
{
    extern __shared__ __align__(1024) char smem[];
    const uint32_t sbase = smem_to_u32(smem);
    const size_t z = blockIdx.z;
    Ah += z * aS; Al += z * aS;
    Bh += z * bS;

    const int tid = threadIdx.x;
    const int wid = tid >> 5;
    const int lane = tid & 31;
    const int bm = blockIdx.y * 128;
    const int bn = blockIdx.x * 256;
    const int wm = wid & 1;          // 2 -> 64 rows
    const int wn = wid >> 1;         // 4 -> 64 cols

    const __half* Ahp = Ah + (size_t)bm * lda;
    const __half* Alp = Al + (size_t)bm * lda;
    const __half* Bhp = Bh + (size_t)bn * ldb;

    const int lr = tid >> 3;         // 0..31
    const int lc = tid & 7;          // 16B chunk in 128B row
    auto load_chunk = [&](int k0, int s) {
        const uint32_t tb = sbase + (uint32_t)s * STAGE_BYTES;
#pragma unroll
        for (int t = 0; t < 2; t++) {
            const __half* base = t ? Alp : Ahp;
#pragma unroll
            for (int rr = 0; rr < 4; rr++) {
                const int row = lr + rr * 32;
                cp16(tb + (uint32_t)t * 16384u + (uint32_t)row * 128u + (uint32_t)((lc ^ (row & 7)) * 16),
                     base + (size_t)row * lda + k0 + lc * 8);
            }
        }
#pragma unroll
        for (int rr = 0; rr < 8; rr++) {
            const int row = lr + rr * 32;
            cp16(tb + 32768u + (uint32_t)row * 128u + (uint32_t)((lc ^ (row & 7)) * 16),
                 Bhp + (size_t)row * ldb + k0 + lc * 8);
        }
    };

    const int q = lane >> 3;
    const int r = lane & 7;
    const uint32_t swz = (uint32_t)(r * 16);
    uint32_t rowA[4];
#pragma unroll
    for (int mt = 0; mt < 4; mt++) rowA[mt] = (uint32_t)(wm * 64 + mt * 16 + (q & 1) * 8 + r) * 128u;
    const uint32_t koffA = (uint32_t)((q >> 1) * 16);
    uint32_t rowB[4];
#pragma unroll
    for (int np = 0; np < 4; np++) rowB[np] = (uint32_t)(wn * 64 + np * 16 + (q >> 1) * 8 + r) * 128u;
    const uint32_t koffB = (uint32_t)((q & 1) * 16);

    float acc[4][8][4];
#pragma unroll
    for (int i = 0; i < 4; i++)
#pragma unroll
        for (int j = 0; j < 8; j++)
#pragma unroll
            for (int e = 0; e < 4; e++) acc[i][j][e] = 0.f;

    const int nchunks = K >> 6;
    load_chunk(0, 0);
    CP_COMMIT();

    for (int i = 0; i < nchunks; i++) {
        const int b = i & 1;
        if (i + 1 < nchunks) {
            load_chunk((i + 1) << 6, (i + 1) & 1);
            CP_COMMIT();
            cp_wait<1>();
        } else {
            cp_wait<0>();
        }
        __syncthreads();

        const uint32_t stg = sbase + (uint32_t)b * STAGE_BYTES;
        const uint32_t aHi = stg;
        const uint32_t aLo = stg + 16384u;
        const uint32_t bHi = stg + 32768u;

#pragma unroll
        for (int ks = 0; ks < 4; ks++) {
            const uint32_t kbA = ((uint32_t)(ks * 32) + koffA) ^ swz;
            const uint32_t kbB = ((uint32_t)(ks * 32) + koffB) ^ swz;
            uint32_t fAh[4][4], fAl[4][4], fBh[8][2];
#pragma unroll
            for (int mt = 0; mt < 4; mt++) {
                LDSM4(fAh[mt][0], fAh[mt][1], fAh[mt][2], fAh[mt][3], aHi + rowA[mt] + kbA);
                LDSM4(fAl[mt][0], fAl[mt][1], fAl[mt][2], fAl[mt][3], aLo + rowA[mt] + kbA);
            }
#pragma unroll
            for (int np = 0; np < 4; np++) {
                LDSM4(fBh[2 * np][0], fBh[2 * np][1], fBh[2 * np + 1][0], fBh[2 * np + 1][1],
                      bHi + rowB[np] + kbB);
            }
#pragma unroll
            for (int mt = 0; mt < 4; mt++)
#pragma unroll
                for (int nt = 0; nt < 8; nt++) mma_f16(acc[mt][nt], fAh[mt], fBh[nt]);
#pragma unroll
            for (int mt = 0; mt < 4; mt++)
#pragma unroll
                for (int nt = 0; nt < 8; nt++) mma_f16(acc[mt][nt], fAl[mt], fBh[nt]);
        }
        __syncthreads();
    }

    const int g  = lane >> 2;
    const int tg = lane & 3;
    if (mode == 0) {
        float* Cz = C + z * cS;
#pragma unroll
        for (int mt = 0; mt < 4; mt++) {
            const int row0 = bm + wm * 64 + mt * 16 + g;
#pragma unroll
            for (int nt = 0; nt < 8; nt++) {
                const int col = bn + wn * 64 + nt * 8 + tg * 2;
                if (col < N) {
                    *(float2*)(Cz + (size_t)row0 * ldc + col) = make_float2(acc[mt][nt][0], acc[mt][nt][1]);
                    *(float2*)(Cz + (size_t)(row0 + 8) * ldc + col) = make_float2(acc[mt][nt][2], acc[mt][nt][3]);
                }
            }
        }
    } else {
        __half* Chz = Chi + z * cS;
        __half* Clz = Clo + z * cS;
#pragma unroll
        for (int mt = 0; mt < 4; mt++) {
            const int row0 = bm + wm * 64 + mt * 16 + g;
#pragma unroll
            for (int nt = 0; nt < 8; nt++) {
                const int col = bn + wn * 64 + nt * 8 + tg * 2;
                if (col < N) {
#pragma unroll
                    for (int half_ = 0; half_ < 2; half_++) {
                        const float v0 = acc[mt][nt][2 * half_];
                        const float v1 = acc[mt][nt][2 * half_ + 1];
                        const __half h0 = __float2half_rn(v0);
                        const __half h1 = __float2half_rn(v1);
                        const __half l0 = __float2half_rn(v0 - __half2float(h0));
                        const __half l1 = __float2half_rn(v1 - __half2float(h1));
                        const size_t off = (size_t)(row0 + 8 * half_) * ldc + col;
                        *(__half2*)(Chz + off) = __half2{h0, h1};
                        *(__half2*)(Clz + off) = __half2{l0, l1};
                    }
                }
            }
        }
    }
}

// =====================================================================
// fp32 -> fp16 hi/lo split (activations; layer-0 input only)
// =====================================================================
__global__ void __launch_bounds__(256) convert_a(
    const float* __restrict__ in, __half* __restrict__ hi,
    __half* __restrict__ lo, int n4)
{
    const int i = blockIdx.x * 256 + threadIdx.x;
    if (i >= n4) return;
    const float4 v = *(const float4*)(in + 4 * (size_t)i);
    __half h0 = __float2half_rn(v.x), h1 = __float2half_rn(v.y);
    __half h2 = __float2half_rn(v.z), h3 = __float2half_rn(v.w);
    __half l0 = __float2half_rn(v.x - __half2float(h0));
    __half l1 = __float2half_rn(v.y - __half2float(h1));
    __half l2 = __float2half_rn(v.z - __half2float(h2));
    __half l3 = __float2half_rn(v.w - __half2float(h3));
    *(__half2*)(hi + 4 * (size_t)i)     = __half2{h0, h1};
    *(__half2*)(hi + 4 * (size_t)i + 2) = __half2{h2, h3};
    *(__half2*)(lo + 4 * (size_t)i)     = __half2{l0, l1};
    *(__half2*)(lo + 4 * (size_t)i + 2) = __half2{l2, l3};
}

// weights: fp16 hi only, zero row padding, batched over blockIdx.z
__global__ void __launch_bounds__(256) convert_w(
    const float* __restrict__ in, __half* __restrict__ hi,
    int rows_in, int K, int n4, size_t inS, size_t outS)
{
    const int i = blockIdx.x * 256 + threadIdx.x;
    if (i >= n4) return;
    const size_t z = blockIdx.z;
    in += z * inS; hi += z * outS;
    const size_t e = 4 * (size_t)i;
    const int row = (int)(e / K);
    float4 v = make_float4(0.f, 0.f, 0.f, 0.f);
    if (row < rows_in) v = *(const float4*)(in + e);
    *(__half2*)(hi + e)     = __half2{__float2half_rn(v.x), __float2half_rn(v.y)};
    *(__half2*)(hi + e + 2) = __half2{__float2half_rn(v.z), __float2half_rn(v.w)};
}

// =====================================================================
// Time-tiled depthwise causal conv (k=4) + bias + silu; plus dt/dA.
// =====================================================================
__global__ void __launch_bounds__(128) conv_dt_kernel(
    const float* __restrict__ conv_w, const float* __restrict__ conv_b,
    const float* __restrict__ dt_bias, const float* __restrict__ A_log,
    int layer)
{
    const int dir  = blockIdx.z;
    const int by   = blockIdx.y;
    const int b    = by >> 5;
    const int t0   = (by & 31) * CONV_TT;
    const int c    = blockIdx.x * 128 + threadIdx.x;
    const int ld   = 2 * layer + dir;
    const float* zx = g_zx[dir];

    __shared__ float S[CONV_TT + 3][128];

    const int start = dir ? t0 : (t0 - 3);
#pragma unroll
    for (int rr = 0; rr < CONV_TT + 3; rr++) {
        const int tt = start + rr;
        float v = 0.f;
        if (tt >= 0 && tt < SEQLEN)
            v = zx[(size_t)((b << 10) + tt) * DIP + DI + c];
        S[rr][threadIdx.x] = v;
    }

    if (blockIdx.x == 0) {
        for (int idx = threadIdx.x; idx < CONV_TT * NH; idx += 128) {
            const int tl = idx >> 4;
            const int h  = idx & 15;
            const int row = (b << 10) + t0 + tl;
            const float raw = zx[(size_t)row * DIP + DI + CD + h] + dt_bias[ld * NH + h];
            const float dt = (raw > 20.f) ? raw : log1pf(expf(raw));
            const float A = -expf(A_log[ld * NH + h]);
            g_dt[dir][row * NH + h] = dt;
            g_dA[dir][row * NH + h] = expf(dt * A);
        }
    }
    __syncthreads();

    const float* w = conv_w + (size_t)ld * CD * KC + (size_t)c * KC;
    float wr[4];
#pragma unroll
    for (int j = 0; j < 4; j++) wr[j] = dir ? w[3 - j] : w[j];
    const float bias = conv_b[(size_t)ld * CD + c];

    float* outp = g_xbc[dir];
#pragma unroll
    for (int i = 0; i < CONV_TT; i++) {
        float acc = bias;
#pragma unroll
        for (int j = 0; j < 4; j++)
            acc = fmaf(wr[j], S[i + j][threadIdx.x], acc);
        const float sv = acc / (1.f + expf(-acc));
        outp[(size_t)((b << 10) + t0 + i) * CD + c] = sv;
    }
}

// =====================================================================
// Scan pass 1 (chunk-local), fully smem-staged via DYNAMIC shared memory
// (53 KB > 48 KB static cap). All 64 steps' x/B/C/dt/dA staged up front
// with cp.async; recurrence has NO global loads and ONE barrier total.
// =====================================================================
__global__ void __launch_bounds__(64) scan_pass1(const float* __restrict__ D_skip, int layer)
{
    extern __shared__ __align__(16) float sdyn[];
    float* Xs  = sdyn;                     // [64][ROWP]
    float* Bsm = sdyn + SCAN_TILE;         // [64][ROWP]
    float* Csm = sdyn + 2 * SCAN_TILE;     // [64][ROWP]
    float* dts = sdyn + 3 * SCAN_TILE;     // [64]
    float* dAs = dts + 64;                 // [64]

    const int chunk = blockIdx.x;
    const int bh    = blockIdx.y;
    const int dir   = blockIdx.z;
    const int p     = threadIdx.x;
    const int b = bh >> 4;
    const int h = bh & 15;

    const float* xbc = g_xbc[dir];
    float* yout = g_y[dir];
    float* cpv  = g_cpv[dir][bh];
    const float Dp = D_skip[(2 * layer + dir) * NH + h];

    // ---- stage: 16 passes; warp covers 4 steps x 16 chunks (bank-spread) ----
    {
        const int ch  = p & 15;          // 16B chunk within 64-float row
        const int st0 = p >> 4;          // 0..3
#pragma unroll
        for (int pass = 0; pass < 16; pass++) {
            const int st = st0 + 4 * pass;
            const int g = chunk * LCHUNK + st;
            const int t = dir ? (SEQLEN - 1 - g) : g;
            const size_t base = (size_t)((b << 10) + t) * CD;
            cp16(smem_to_u32(Xs  + st * ROWP + ch * 4), xbc + base + h * 64 + ch * 4);
            cp16(smem_to_u32(Bsm + st * ROWP + ch * 4), xbc + base + DI + ch * 4);
            cp16(smem_to_u32(Csm + st * ROWP + ch * 4), xbc + base + DI + DS + ch * 4);
        }
        const int g = chunk * LCHUNK + p;
        const int t = dir ? (SEQLEN - 1 - g) : g;
        const int row = (b << 10) + t;
        dts[p] = g_dt[dir][row * NH + h];
        dAs[p] = g_dA[dir][row * NH + h];
    }
    CP_COMMIT();
    cp_wait<0>();
    __syncthreads();

    float s[64];
#pragma unroll
    for (int nn = 0; nn < 64; nn++) s[nn] = 0.f;
    float cp_ = 1.f;

    for (int st = 0; st < LCHUNK; ++st) {
        const int g = chunk * LCHUNK + st;
        const int t = dir ? (SEQLEN - 1 - g) : g;
        const int row = (b << 10) + t;

        const float dA_c = dAs[st];
        const float dt_c = dts[st];
        const float xv_c = Xs[st * ROWP + p];

        cp_ *= dA_c;
        if (p == 0) cpv[g] = cp_;

        const float coef = dt_c * xv_c;
        float y0 = 0.f, y1 = 0.f, y2 = 0.f, y3 = 0.f;
        const float4* B4 = (const float4*)(Bsm + st * ROWP);
        const float4* C4 = (const float4*)(Csm + st * ROWP);
#pragma unroll
        for (int qq = 0; qq < 16; qq++) {
            const float4 bb = B4[qq];
            const float4 cc = C4[qq];
            float t0 = fmaf(s[4 * qq + 0], dA_c, coef * bb.x); s[4 * qq + 0] = t0; y0 = fmaf(t0, cc.x, y0);
            float t1 = fmaf(s[4 * qq + 1], dA_c, coef * bb.y); s[4 * qq + 1] = t1; y1 = fmaf(t1, cc.y, y1);
            float t2 = fmaf(s[4 * qq + 2], dA_c, coef * bb.z); s[4 * qq + 2] = t2; y2 = fmaf(t2, cc.z, y2);
            float t3 = fmaf(s[4 * qq + 3], dA_c, coef * bb.w); s[4 * qq + 3] = t3; y3 = fmaf(t3, cc.w, y3);
        }
        yout[(size_t)row * DI + h * 64 + p] = (y0 + y1) + (y2 + y3) + Dp * xv_c;
    }

    float* st_ = g_state[dir][bh][chunk] + p * 64;
#pragma unroll
    for (int nn = 0; nn < 64; nn += 4)
        *(float4*)(st_ + nn) = make_float4(s[nn], s[nn + 1], s[nn + 2], s[nn + 3]);
}

// =====================================================================
// Scan pass 2: combine chunk states (in place -> s_start per chunk)
// =====================================================================
__global__ void __launch_bounds__(256) scan_pass2()
{
    const int u = blockIdx.x;
    const int dir = u >> 6;
    const int bh  = u & 63;
    const int off = threadIdx.x * 16;

    float4 c0 = make_float4(0.f, 0.f, 0.f, 0.f), c1 = c0, c2 = c0, c3 = c0;

    for (int c = 0; c < NCHUNK; c++) {
        float4* st = (float4*)(g_state[dir][bh][c] + off);
        const float P = g_cpv[dir][bh][c * LCHUNK + LCHUNK - 1];
        float4 l0 = st[0], l1 = st[1], l2 = st[2], l3 = st[3];
        st[0] = c0; st[1] = c1; st[2] = c2; st[3] = c3;
        c0.x = fmaf(P, c0.x, l0.x); c0.y = fmaf(P, c0.y, l0.y);
        c0.z = fmaf(P, c0.z, l0.z); c0.w = fmaf(P, c0.w, l0.w);
        c1.x = fmaf(P, c1.x, l1.x); c1.y = fmaf(P, c1.y, l1.y);
        c1.z = fmaf(P, c1.z, l1.z); c1.w = fmaf(P, c1.w, l1.w);
        c2.x = fmaf(P, c2.x, l2.x); c2.y = fmaf(P, c2.y, l2.y);
        c2.z = fmaf(P, c2.z, l2.z); c2.w = fmaf(P, c2.w, l2.w);
        c3.x = fmaf(P, c3.x, l3.x); c3.y = fmaf(P, c3.y, l3.y);
        c3.z = fmaf(P, c3.z, l3.z); c3.w = fmaf(P, c3.w, l3.w);
    }
}

// =====================================================================
// Scan pass 3: y += cp_t * (s_start . C_t); double-buffered C tile,
// one barrier per 4-step group.
// =====================================================================
__global__ void __launch_bounds__(256) scan_pass3()
{
    const int chunk = blockIdx.x + 1;
    const int bh    = blockIdx.y;
    const int dir   = blockIdx.z;
    const int p  = threadIdx.x & 63;
    const int tg = threadIdx.x >> 6;
    const int b = bh >> 4;
    const int h = bh & 15;

    __shared__ float Ss[64][68];
    __shared__ float Cs[2][4][64];
    __shared__ float cps[2][4];

    const float* st = g_state[dir][bh][chunk];
    for (int i = threadIdx.x; i < 4096; i += 256)
        Ss[i >> 6][i & 63] = st[i];

    const float* xbc = g_xbc[dir];
    float* yout = g_y[dir];

    auto load_group = [&](int gi, int buf) {
        const int g = chunk * LCHUNK + 4 * gi + tg;
        const int t = dir ? (SEQLEN - 1 - g) : g;
        const int row = (b << 10) + t;
        Cs[buf][tg][p] = xbc[(size_t)row * CD + DI + DS + p];
        if (p == 0) cps[buf][tg] = g_cpv[dir][bh][g];
    };

    load_group(0, 0);

    for (int gi = 0; gi < LCHUNK / 4; gi++) {
        const int buf = gi & 1;
        __syncthreads();
        if (gi + 1 < LCHUNK / 4) load_group(gi + 1, buf ^ 1);

        const int g = chunk * LCHUNK + 4 * gi + tg;
        const int t = dir ? (SEQLEN - 1 - g) : g;
        const int row = (b << 10) + t;

        float a0 = 0.f, a1 = 0.f, a2 = 0.f, a3 = 0.f;
#pragma unroll
        for (int nn = 0; nn < 64; nn += 4) {
            const float4 sv = *(const float4*)&Ss[p][nn];
            const float4 cv = *(const float4*)&Cs[buf][tg][nn];
            a0 = fmaf(sv.x, cv.x, a0);
            a1 = fmaf(sv.y, cv.y, a1);
            a2 = fmaf(sv.z, cv.z, a2);
            a3 = fmaf(sv.w, cv.w, a3);
        }
        yout[(size_t)row * DI + h * 64 + p] += cps[buf][tg] * ((a0 + a1) + (a2 + a3));
    }
}

// ---------------- block reduce helper ----------------
__device__ __forceinline__ float block_reduce_sum_256(float v, float* red)
{
#pragma unroll
    for (int o = 16; o > 0; o >>= 1) v += __shfl_xor_sync(0xffffffffu, v, o);
    if ((threadIdx.x & 31) == 0) red[threadIdx.x >> 5] = v;
    __syncthreads();
    float total = 0.f;
#pragma unroll
    for (int i = 0; i < 8; i++) total += red[i];
    return total;
}

// =====================================================================
// gated RMSNorm over D_INNER; emits fp16 hi/lo directly into GEMM A bufs.
// =====================================================================
__global__ void __launch_bounds__(256) gate_norm_kernel(const float* __restrict__ gnorm_w, int layer)
{
    const int row = blockIdx.x;
    const int dir = blockIdx.y;
    const float* y = g_y[dir] + (size_t)row * DI;
    const float* z = g_zx[dir] + (size_t)row * DIP;
    const float* gwp = gnorm_w + (size_t)(2 * layer + dir) * DI;
    const int e0 = threadIdx.x * 4;

    __shared__ float red[8];
    const float4 yv = *(const float4*)(y + e0);
    const float4 zv = *(const float4*)(z + e0);
    float v[4];
    v[0] = yv.x * (zv.x / (1.f + expf(-zv.x)));
    v[1] = yv.y * (zv.y / (1.f + expf(-zv.y)));
    v[2] = yv.z * (zv.z / (1.f + expf(-zv.z)));
    v[3] = yv.w * (zv.w / (1.f + expf(-zv.w)));
    float ss = fmaf(v[0], v[0], fmaf(v[1], v[1], fmaf(v[2], v[2], v[3] * v[3])));

    const float total = block_reduce_sum_256(ss, red);
    const float scale = rsqrtf(total * (1.f / (float)DI) + 1e-5f);

    const float4 gv = *(const float4*)(gwp + e0);
    float o[4] = { v[0] * scale * gv.x, v[1] * scale * gv.y,
                   v[2] * scale * gv.z, v[3] * scale * gv.w };

    __half hb[4], lb[4];
#pragma unroll
    for (int j = 0; j < 4; j++) {
        hb[j] = __float2half_rn(o[j]);
        lb[j] = __float2half_rn(o[j] - __half2float(hb[j]));
    }
    const size_t off = (size_t)dir * BL * DI + (size_t)row * DI + e0;
    *(__half2*)(g_ah + off)     = __half2{hb[0], hb[1]};
    *(__half2*)(g_ah + off + 2) = __half2{hb[2], hb[3]};
    *(__half2*)(g_al + off)     = __half2{lb[0], lb[1]};
    *(__half2*)(g_al + off + 2) = __half2{lb[2], lb[3]};
}

// =====================================================================
// residual RMSNorm over D_MODEL (sums both outproj split-K halves);
// emits fp32 hout AND fp16 hi/lo (next layer's in_proj A).
// =====================================================================
__global__ void __launch_bounds__(256) resid_norm_kernel(
    const float* __restrict__ hin, const float* __restrict__ nw, float* __restrict__ hout)
{
    const int row = blockIdx.x;
    const int tid = threadIdx.x;
    __shared__ float red[8];

    const size_t base = (size_t)row * DM;
    const float v0 = hin[base + tid]       + g_tmp[0][base + tid]       + g_tmp[1][base + tid];
    const float v1 = hin[base + tid + 256] + g_tmp[0][base + tid + 256] + g_tmp[1][base + tid + 256];
    const float total = block_reduce_sum_256(v0 * v0 + v1 * v1, red);
    const float scale = rsqrtf(total * (1.f / (float)DM) + 1.1920929e-07f);

    const float o0 = v0 * scale * nw[tid];
    const float o1 = v1 * scale * nw[tid + 256];
    hout[base + tid]       = o0;
    hout[base + tid + 256] = o1;

    const __half h0 = __float2half_rn(o0);
    const __half h1 = __float2half_rn(o1);
    g_ah[base + tid]       = h0;
    g_ah[base + tid + 256] = h1;
    g_al[base + tid]       = __float2half_rn(o0 - __half2float(h0));
    g_al[base + tid + 256] = __float2half_rn(o1 - __half2float(h1));
}

// =====================================================================
// Host launcher
// =====================================================================
extern "C" void kernel_launch(void* const* d_in, const int* in_sizes, int n_in,
                              void* d_out, int out_size)
{
    (void)in_sizes; (void)n_in; (void)out_size;
    const float* x    = (const float*)d_in[0];
    const float* Wi   = (const float*)d_in[1];
    const float* Wc   = (const float*)d_in[2];
    const float* bc   = (const float*)d_in[3];
    const float* dtb  = (const float*)d_in[4];
    const float* Alog = (const float*)d_in[5];
    const float* Dsk  = (const float*)d_in[6];
    const float* gw   = (const float*)d_in[7];
    const float* Wm   = (const float*)d_in[8];
    const float* nw   = (const float*)d_in[9];
    const float* Wo   = (const float*)d_in[10];
    float* out = (float*)d_out;

    cudaFuncSetAttribute(gemm_tc, cudaFuncAttributeMaxDynamicSharedMemorySize, GEMM_SMEM);
    cudaFuncSetAttribute(scan_pass1, cudaFuncAttributeMaxDynamicSharedMemorySize, SCAN_SMEM);

    float *zx0, *tmp, *hbuf;
    __half *ah, *al, *ch, *cl, *wih, *wmh, *woh;
    cudaGetSymbolAddress((void**)&zx0,  g_zx);
    cudaGetSymbolAddress((void**)&tmp,  g_tmp);
    cudaGetSymbolAddress((void**)&hbuf, g_h);
    cudaGetSymbolAddress((void**)&ah,   g_ah);
    cudaGetSymbolAddress((void**)&al,   g_al);
    cudaGetSymbolAddress((void**)&ch,   g_ch);
    cudaGetSymbolAddress((void**)&cl,   g_cl);
    cudaGetSymbolAddress((void**)&wih,  g_wi_h);
    cudaGetSymbolAddress((void**)&wmh,  g_wm_h);
    cudaGetSymbolAddress((void**)&woh,  g_wo_h);

    // ---- convert all weights to fp16 hi (batched over z) ----
    convert_w<<<dim3((DIPP * DM / 4 + 255) / 256, 1, 4), 256>>>(
        Wi, wih, DIP, DM, DIPP * DM / 4, (size_t)DIP * DM, (size_t)DIPP * DM);
    convert_w<<<dim3((DM * DI / 4 + 255) / 256, 1, 4), 256>>>(
        Wm, wmh, DM, DI, DM * DI / 4, (size_t)DM * DI, (size_t)DM * DI);
    convert_w<<<dim3((DM * DI / 4 + 255) / 256, 1, 1), 256>>>(
        Wo, woh, DM, DI, DM * DI / 4, 0, 0);

    for (int l = 0; l < NLAYERS; l++) {
        const float* hin = (l == 0) ? x : hbuf;
        float* hout = (l == NLAYERS - 1) ? out : hbuf;

        // in_proj A: layer 0 converts x; layer >0 uses resid_norm's fp16 output
        if (l == 0)
            convert_a<<<(BL * DM / 4 + 255) / 256, 256>>>(hin, ah, al, BL * DM / 4);
        gemm_tc<<<dim3(DIPP / 256, BL / 128, 2), 256, GEMM_SMEM>>>(
            ah, al, wih + (size_t)(2 * l) * DIPP * DM,
            zx0, nullptr, nullptr,
            DIP, DM, DM, DM, DIP,
            0, (size_t)DIPP * DM, (size_t)BL * DIP, 0);

        conv_dt_kernel<<<dim3(CD / 128, BL / CONV_TT, 2), 128>>>(Wc, bc, dtb, Alog, l);
        scan_pass1<<<dim3(NCHUNK, 64, 2), 64, SCAN_SMEM>>>(Dsk, l);
        scan_pass2<<<128, 256>>>();
        scan_pass3<<<dim3(NCHUNK - 1, 64, 2), 256>>>();
        gate_norm_kernel<<<dim3(BL, 2), 256>>>(gw, l);   // emits fp16 into ah/al

        // mout, both dirs in one launch; fp16 hi/lo epilogue into ch/cl
        gemm_tc<<<dim3(DM / 256, BL / 128, 2), 256, GEMM_SMEM>>>(
            ah, al, wmh + (size_t)(2 * l) * DM * DI,
            nullptr, ch, cl,
            DM, DI, DI, DI, DI,
            (size_t)BL * DI, (size_t)DM * DI, (size_t)DM, 1);

        // outproj: split-K over z (K halves of 512), fp32 halves into g_tmp
        gemm_tc<<<dim3(DM / 256, BL / 128, 2), 256, GEMM_SMEM>>>(
            ch, cl, woh,
            tmp, nullptr, nullptr,
            DM, DM /*K=512*/, DI, DI, DM,
            (size_t)DM, (size_t)DM, (size_t)BL * DM, 0);

        resid_norm_kernel<<<BL, 256>>>(hin, nw + (size_t)l * DM, hout);
    }
}

// round 17
// speedup vs baseline: 1.0219x; 1.0219x over previous
#include <cuda_runtime.h>
#include <cuda_fp16.h>
#include <math.h>
#include <stdint.h>

// ---------------- problem constants ----------------
#define BATCH   4
#define SEQLEN  1024
#define BL      4096            // BATCH*SEQLEN
#define DM      512             // D_MODEL
#define DI      1024            // D_INNER
#define DS      64              // D_STATE
#define NH      16              // NHEADS
#define HD      64              // HEADDIM
#define CD      1152            // CONV_DIM = DI + 2*DS
#define DIP     2192            // D_IN_PROJ
#define DIPP    2304            // DIP padded to 256-multiple
#define KC      4               // K_CONV
#define NLAYERS 2

#define NCHUNK  16
#define LCHUNK  (SEQLEN / NCHUNK)   // 64
#define CONV_TT 32                  // time tile for conv kernel

// ---------------- scratch (device globals; no allocation) ----------------
__device__ float g_zx [2][(size_t)BL*DIP];
__device__ float g_xbc[2][(size_t)BL*CD];
__device__ float g_dt [2][BL*NH];
__device__ float g_dA [2][BL*NH];
__device__ float g_y  [2][(size_t)BL*DI];
__device__ float g_tmp[2][(size_t)BL*DM];   // outproj split-K halves
__device__ float g_h  [(size_t)BL*DM];
__device__ float g_state[2][64][NCHUNK][64*64];
__device__ float g_cpv[2][64][SEQLEN];

// fp16 hi/lo split buffers (A side gets hi+lo, weights hi only)
__device__ __half g_ah[2*(size_t)BL*DI];   // GEMM A (activations)
__device__ __half g_al[2*(size_t)BL*DI];
__device__ __half g_ch[(size_t)BL*DI];     // mout output = outproj input
__device__ __half g_cl[(size_t)BL*DI];
__device__ __half g_wi_h[4][(size_t)DIPP*DM];
__device__ __half g_wm_h[4][(size_t)DM*DI];
__device__ __half g_wo_h[(size_t)DM*DI];

// =====================================================================
// low-level helpers
// =====================================================================
__device__ __forceinline__ uint32_t smem_to_u32(const void* p) {
    uint32_t a;
    asm("{ .reg .u64 t; cvta.to.shared.u64 t, %1; cvt.u32.u64 %0, t; }" : "=r"(a) : "l"(p));
    return a;
}
__device__ __forceinline__ void cp16(uint32_t dst, const void* src) {
    asm volatile("cp.async.cg.shared.global [%0], [%1], 16;" :: "r"(dst), "l"(src));
}
#define CP_COMMIT() asm volatile("cp.async.commit_group;" ::: "memory")
template <int N> __device__ __forceinline__ void cp_wait() {
    asm volatile("cp.async.wait_group %0;" :: "n"(N) : "memory");
}
#define LDSM4(R0, R1, R2, R3, addr) \
    asm volatile("ldmatrix.sync.aligned.m8n8.x4.shared.b16 {%0,%1,%2,%3}, [%4];" \
        : "=r"(R0), "=r"(R1), "=r"(R2), "=r"(R3) : "r"(addr))
__device__ __forceinline__ void mma_f16(float* c, const uint32_t* a, const uint32_t* b) {
    asm volatile("mma.sync.aligned.m16n8k16.row.col.f32.f16.f16.f32 "
        "{%0,%1,%2,%3}, {%4,%5,%6,%7}, {%8,%9}, {%0,%1,%2,%3};"
        : "+f"(c[0]), "+f"(c[1]), "+f"(c[2]), "+f"(c[3])
        : "r"(a[0]), "r"(a[1]), "r"(a[2]), "r"(a[3]), "r"(b[0]), "r"(b[1]));
}

#define STAGE_BYTES 65536u     // Ah 16K | Al 16K | Bh 32K
#define GEMM_SMEM   196608     // 3 stages

// =====================================================================
// HMMA fp16x2 GEMM: C[M,N] = A[M,K]*B[N,K]^T; A split hi/lo, B hi only.
// C = Ah*Bh + Al*Bh  (dropped A*Bl ~ 2^-12 relative).
// CTA tile 128x256, 8 warps (2x4), warp tile 64x64, BK=64, 3 stages
// (prefetch depth 2 hides L2 service latency).
// grid (ceil(N/256), M/128, Z). lda/ldb allow K-slices (split-K).
// mode 0: fp32 C; mode 1: fp16 hi/lo split into Chi/Clo.
// =====================================================================
__global__ void __launch_bounds__(256) gemm_tc(
    const __half* __restrict__ Ah, const __half* __restrict__ Al,
    const __half* __restrict__ Bh,
    float* __restrict__ C, __half* __restrict__ Chi, __half* __restrict__ Clo,
    int N, int K, int lda, int ldb, int ldc,
    size_t aS, size_t bS, size_t cS, int mode)
{
    extern __shared__ __align__(1024) char smem[];
    const uint32_t sbase = smem_to_u32(smem);
    const size_t z = blockIdx.z;
    Ah += z * aS; Al += z * aS;
    Bh += z * bS;

    const int tid = threadIdx.x;
    const int wid = tid >> 5;
    const int lane = tid & 31;
    const int bm = blockIdx.y * 128;
    const int bn = blockIdx.x * 256;
    const int wm = wid & 1;          // 2 -> 64 rows
    const int wn = wid >> 1;         // 4 -> 64 cols

    const __half* Ahp = Ah + (size_t)bm * lda;
    const __half* Alp = Al + (size_t)bm * lda;
    const __half* Bhp = Bh + (size_t)bn * ldb;

    const int lr = tid >> 3;         // 0..31
    const int lc = tid & 7;          // 16B chunk in 128B row
    auto load_chunk = [&](int k0, int s) {
        const uint32_t tb = sbase + (uint32_t)s * STAGE_BYTES;
#pragma unroll
        for (int t = 0; t < 2; t++) {
            const __half* base = t ? Alp : Ahp;
#pragma unroll
            for (int rr = 0; rr < 4; rr++) {
                const int row = lr + rr * 32;
                cp16(tb + (uint32_t)t * 16384u + (uint32_t)row * 128u + (uint32_t)((lc ^ (row & 7)) * 16),
                     base + (size_t)row * lda + k0 + lc * 8);
            }
        }
#pragma unroll
        for (int rr = 0; rr < 8; rr++) {
            const int row = lr + rr * 32;
            cp16(tb + 32768u + (uint32_t)row * 128u + (uint32_t)((lc ^ (row & 7)) * 16),
                 Bhp + (size_t)row * ldb + k0 + lc * 8);
        }
    };

    const int q = lane >> 3;
    const int r = lane & 7;
    const uint32_t swz = (uint32_t)(r * 16);
    uint32_t rowA[4];
#pragma unroll
    for (int mt = 0; mt < 4; mt++) rowA[mt] = (uint32_t)(wm * 64 + mt * 16 + (q & 1) * 8 + r) * 128u;
    const uint32_t koffA = (uint32_t)((q >> 1) * 16);
    uint32_t rowB[4];
#pragma unroll
    for (int np = 0; np < 4; np++) rowB[np] = (uint32_t)(wn * 64 + np * 16 + (q >> 1) * 8 + r) * 128u;
    const uint32_t koffB = (uint32_t)((q & 1) * 16);

    float acc[4][8][4];
#pragma unroll
    for (int i = 0; i < 4; i++)
#pragma unroll
        for (int j = 0; j < 8; j++)
#pragma unroll
            for (int e = 0; e < 4; e++) acc[i][j][e] = 0.f;

    const int nchunks = K >> 6;
    load_chunk(0, 0);
    CP_COMMIT();
    if (nchunks > 1) { load_chunk(64, 1); CP_COMMIT(); }

    for (int i = 0; i < nchunks; i++) {
        // ensure group i is complete (at most 1 newer group may stay in flight)
        if (i + 1 < nchunks) cp_wait<1>(); else cp_wait<0>();
        __syncthreads();   // also: all threads done computing chunk i-1

        if (i + 2 < nchunks) {
            load_chunk((i + 2) << 6, (i + 2) % 3);   // overwrites buffer of chunk i-1
            CP_COMMIT();
        }

        const uint32_t stg = sbase + (uint32_t)(i % 3) * STAGE_BYTES;
        const uint32_t aHi = stg;
        const uint32_t aLo = stg + 16384u;
        const uint32_t bHi = stg + 32768u;

#pragma unroll
        for (int ks = 0; ks < 4; ks++) {
            const uint32_t kbA = ((uint32_t)(ks * 32) + koffA) ^ swz;
            const uint32_t kbB = ((uint32_t)(ks * 32) + koffB) ^ swz;
            uint32_t fAh[4][4], fAl[4][4], fBh[8][2];
#pragma unroll
            for (int mt = 0; mt < 4; mt++) {
                LDSM4(fAh[mt][0], fAh[mt][1], fAh[mt][2], fAh[mt][3], aHi + rowA[mt] + kbA);
                LDSM4(fAl[mt][0], fAl[mt][1], fAl[mt][2], fAl[mt][3], aLo + rowA[mt] + kbA);
            }
#pragma unroll
            for (int np = 0; np < 4; np++) {
                LDSM4(fBh[2 * np][0], fBh[2 * np][1], fBh[2 * np + 1][0], fBh[2 * np + 1][1],
                      bHi + rowB[np] + kbB);
            }
#pragma unroll
            for (int mt = 0; mt < 4; mt++)
#pragma unroll
                for (int nt = 0; nt < 8; nt++) mma_f16(acc[mt][nt], fAh[mt], fBh[nt]);
#pragma unroll
            for (int mt = 0; mt < 4; mt++)
#pragma unroll
                for (int nt = 0; nt < 8; nt++) mma_f16(acc[mt][nt], fAl[mt], fBh[nt]);
        }
    }
    __syncthreads();

    const int g  = lane >> 2;
    const int tg = lane & 3;
    if (mode == 0) {
        float* Cz = C + z * cS;
#pragma unroll
        for (int mt = 0; mt < 4; mt++) {
            const int row0 = bm + wm * 64 + mt * 16 + g;
#pragma unroll
            for (int nt = 0; nt < 8; nt++) {
                const int col = bn + wn * 64 + nt * 8 + tg * 2;
                if (col < N) {
                    *(float2*)(Cz + (size_t)row0 * ldc + col) = make_float2(acc[mt][nt][0], acc[mt][nt][1]);
                    *(float2*)(Cz + (size_t)(row0 + 8) * ldc + col) = make_float2(acc[mt][nt][2], acc[mt][nt][3]);
                }
            }
        }
    } else {
        __half* Chz = Chi + z * cS;
        __half* Clz = Clo + z * cS;
#pragma unroll
        for (int mt = 0; mt < 4; mt++) {
            const int row0 = bm + wm * 64 + mt * 16 + g;
#pragma unroll
            for (int nt = 0; nt < 8; nt++) {
                const int col = bn + wn * 64 + nt * 8 + tg * 2;
                if (col < N) {
#pragma unroll
                    for (int half_ = 0; half_ < 2; half_++) {
                        const float v0 = acc[mt][nt][2 * half_];
                        const float v1 = acc[mt][nt][2 * half_ + 1];
                        const __half h0 = __float2half_rn(v0);
                        const __half h1 = __float2half_rn(v1);
                        const __half l0 = __float2half_rn(v0 - __half2float(h0));
                        const __half l1 = __float2half_rn(v1 - __half2float(h1));
                        const size_t off = (size_t)(row0 + 8 * half_) * ldc + col;
                        *(__half2*)(Chz + off) = __half2{h0, h1};
                        *(__half2*)(Clz + off) = __half2{l0, l1};
                    }
                }
            }
        }
    }
}

// =====================================================================
// fp32 -> fp16 hi/lo split (activations; layer-0 input only)
// =====================================================================
__global__ void __launch_bounds__(256) convert_a(
    const float* __restrict__ in, __half* __restrict__ hi,
    __half* __restrict__ lo, int n4)
{
    const int i = blockIdx.x * 256 + threadIdx.x;
    if (i >= n4) return;
    const float4 v = *(const float4*)(in + 4 * (size_t)i);
    __half h0 = __float2half_rn(v.x), h1 = __float2half_rn(v.y);
    __half h2 = __float2half_rn(v.z), h3 = __float2half_rn(v.w);
    __half l0 = __float2half_rn(v.x - __half2float(h0));
    __half l1 = __float2half_rn(v.y - __half2float(h1));
    __half l2 = __float2half_rn(v.z - __half2float(h2));
    __half l3 = __float2half_rn(v.w - __half2float(h3));
    *(__half2*)(hi + 4 * (size_t)i)     = __half2{h0, h1};
    *(__half2*)(hi + 4 * (size_t)i + 2) = __half2{h2, h3};
    *(__half2*)(lo + 4 * (size_t)i)     = __half2{l0, l1};
    *(__half2*)(lo + 4 * (size_t)i + 2) = __half2{l2, l3};
}

// weights: fp16 hi only, zero row padding, batched over blockIdx.z
__global__ void __launch_bounds__(256) convert_w(
    const float* __restrict__ in, __half* __restrict__ hi,
    int rows_in, int K, int n4, size_t inS, size_t outS)
{
    const int i = blockIdx.x * 256 + threadIdx.x;
    if (i >= n4) return;
    const size_t z = blockIdx.z;
    in += z * inS; hi += z * outS;
    const size_t e = 4 * (size_t)i;
    const int row = (int)(e / K);
    float4 v = make_float4(0.f, 0.f, 0.f, 0.f);
    if (row < rows_in) v = *(const float4*)(in + e);
    *(__half2*)(hi + e)     = __half2{__float2half_rn(v.x), __float2half_rn(v.y)};
    *(__half2*)(hi + e + 2) = __half2{__float2half_rn(v.z), __float2half_rn(v.w)};
}

// =====================================================================
// Time-tiled depthwise causal conv (k=4) + bias + silu; plus dt/dA.
// =====================================================================
__global__ void __launch_bounds__(128) conv_dt_kernel(
    const float* __restrict__ conv_w, const float* __restrict__ conv_b,
    const float* __restrict__ dt_bias, const float* __restrict__ A_log,
    int layer)
{
    const int dir  = blockIdx.z;
    const int by   = blockIdx.y;
    const int b    = by >> 5;
    const int t0   = (by & 31) * CONV_TT;
    const int c    = blockIdx.x * 128 + threadIdx.x;
    const int ld   = 2 * layer + dir;
    const float* zx = g_zx[dir];

    __shared__ float S[CONV_TT + 3][128];

    const int start = dir ? t0 : (t0 - 3);
#pragma unroll
    for (int rr = 0; rr < CONV_TT + 3; rr++) {
        const int tt = start + rr;
        float v = 0.f;
        if (tt >= 0 && tt < SEQLEN)
            v = zx[(size_t)((b << 10) + tt) * DIP + DI + c];
        S[rr][threadIdx.x] = v;
    }

    if (blockIdx.x == 0) {
        for (int idx = threadIdx.x; idx < CONV_TT * NH; idx += 128) {
            const int tl = idx >> 4;
            const int h  = idx & 15;
            const int row = (b << 10) + t0 + tl;
            const float raw = zx[(size_t)row * DIP + DI + CD + h] + dt_bias[ld * NH + h];
            const float dt = (raw > 20.f) ? raw : log1pf(expf(raw));
            const float A = -expf(A_log[ld * NH + h]);
            g_dt[dir][row * NH + h] = dt;
            g_dA[dir][row * NH + h] = expf(dt * A);
        }
    }
    __syncthreads();

    const float* w = conv_w + (size_t)ld * CD * KC + (size_t)c * KC;
    float wr[4];
#pragma unroll
    for (int j = 0; j < 4; j++) wr[j] = dir ? w[3 - j] : w[j];
    const float bias = conv_b[(size_t)ld * CD + c];

    float* outp = g_xbc[dir];
#pragma unroll
    for (int i = 0; i < CONV_TT; i++) {
        float acc = bias;
#pragma unroll
        for (int j = 0; j < 4; j++)
            acc = fmaf(wr[j], S[i + j][threadIdx.x], acc);
        const float sv = acc / (1.f + expf(-acc));
        outp[(size_t)((b << 10) + t0 + i) * CD + c] = sv;
    }
}

// =====================================================================
// Scan pass 1 (chunk-local), register-pipelined (R12 config):
// prefetch next step's operands, double-buffered B/C smem, one barrier/step.
// =====================================================================
__global__ void __launch_bounds__(64) scan_pass1(const float* __restrict__ D_skip, int layer)
{
    const int chunk = blockIdx.x;
    const int bh    = blockIdx.y;
    const int dir   = blockIdx.z;
    const int p     = threadIdx.x;
    const int b = bh >> 4;
    const int h = bh & 15;

    const float* xbc = g_xbc[dir];
    const float* dtv = g_dt[dir];
    const float* dAv = g_dA[dir];
    float* yout = g_y[dir];
    const float Dp = D_skip[(2 * layer + dir) * NH + h];

    __shared__ float Bs[2][64];
    __shared__ float Cs[2][64];

    float s[64];
#pragma unroll
    for (int nn = 0; nn < 64; nn++) s[nn] = 0.f;
    float cp = 1.f;

    int g = chunk * LCHUNK;
    int t = dir ? (SEQLEN - 1 - g) : g;
    int row = (b << 10) + t;
    size_t base = (size_t)row * CD;
    float xv = xbc[base + h * 64 + p];
    float Bv = xbc[base + DI + p];
    float Cv = xbc[base + DI + DS + p];
    float dtr = dtv[row * NH + h];
    float dAr = dAv[row * NH + h];

    for (int step = 0; step < LCHUNK; ++step) {
        const int buf = step & 1;
        Bs[buf][p] = Bv;
        Cs[buf][p] = Cv;
        const float xv_c = xv, dt_c = dtr, dA_c = dAr;
        const int row_c = row;

        if (step + 1 < LCHUNK) {
            const int g2 = chunk * LCHUNK + step + 1;
            const int t2 = dir ? (SEQLEN - 1 - g2) : g2;
            row = (b << 10) + t2;
            const size_t b2 = (size_t)row * CD;
            xv  = xbc[b2 + h * 64 + p];
            Bv  = xbc[b2 + DI + p];
            Cv  = xbc[b2 + DI + DS + p];
            dtr = dtv[row * NH + h];
            dAr = dAv[row * NH + h];
        }
        __syncthreads();

        cp *= dA_c;
        if (p == 0) g_cpv[dir][bh][chunk * LCHUNK + step] = cp;

        const float coef = dt_c * xv_c;
        float y0 = 0.f, y1 = 0.f, y2 = 0.f, y3 = 0.f;
        const float4* B4 = (const float4*)Bs[buf];
        const float4* C4 = (const float4*)Cs[buf];
#pragma unroll
        for (int qq = 0; qq < 16; qq++) {
            const float4 bb = B4[qq];
            const float4 cc = C4[qq];
            float t0 = fmaf(s[4 * qq + 0], dA_c, coef * bb.x); s[4 * qq + 0] = t0; y0 = fmaf(t0, cc.x, y0);
            float t1 = fmaf(s[4 * qq + 1], dA_c, coef * bb.y); s[4 * qq + 1] = t1; y1 = fmaf(t1, cc.y, y1);
            float t2 = fmaf(s[4 * qq + 2], dA_c, coef * bb.z); s[4 * qq + 2] = t2; y2 = fmaf(t2, cc.z, y2);
            float t3 = fmaf(s[4 * qq + 3], dA_c, coef * bb.w); s[4 * qq + 3] = t3; y3 = fmaf(t3, cc.w, y3);
        }
        yout[(size_t)row_c * DI + h * 64 + p] = (y0 + y1) + (y2 + y3) + Dp * xv_c;
    }

    float* st = g_state[dir][bh][chunk] + p * 64;
#pragma unroll
    for (int nn = 0; nn < 64; nn += 4)
        *(float4*)(st + nn) = make_float4(s[nn], s[nn + 1], s[nn + 2], s[nn + 3]);
}

// =====================================================================
// Scan pass 2: combine chunk states (in place -> s_start per chunk)
// =====================================================================
__global__ void __launch_bounds__(256) scan_pass2()
{
    const int u = blockIdx.x;
    const int dir = u >> 6;
    const int bh  = u & 63;
    const int off = threadIdx.x * 16;

    float4 c0 = make_float4(0.f, 0.f, 0.f, 0.f), c1 = c0, c2 = c0, c3 = c0;

    for (int c = 0; c < NCHUNK; c++) {
        float4* st = (float4*)(g_state[dir][bh][c] + off);
        const float P = g_cpv[dir][bh][c * LCHUNK + LCHUNK - 1];
        float4 l0 = st[0], l1 = st[1], l2 = st[2], l3 = st[3];
        st[0] = c0; st[1] = c1; st[2] = c2; st[3] = c3;
        c0.x = fmaf(P, c0.x, l0.x); c0.y = fmaf(P, c0.y, l0.y);
        c0.z = fmaf(P, c0.z, l0.z); c0.w = fmaf(P, c0.w, l0.w);
        c1.x = fmaf(P, c1.x, l1.x); c1.y = fmaf(P, c1.y, l1.y);
        c1.z = fmaf(P, c1.z, l1.z); c1.w = fmaf(P, c1.w, l1.w);
        c2.x = fmaf(P, c2.x, l2.x); c2.y = fmaf(P, c2.y, l2.y);
        c2.z = fmaf(P, c2.z, l2.z); c2.w = fmaf(P, c2.w, l2.w);
        c3.x = fmaf(P, c3.x, l3.x); c3.y = fmaf(P, c3.y, l3.y);
        c3.z = fmaf(P, c3.z, l3.z); c3.w = fmaf(P, c3.w, l3.w);
    }
}

// =====================================================================
// Scan pass 3: y += cp_t * (s_start . C_t); double-buffered C tile,
// one barrier per 4-step group.
// =====================================================================
__global__ void __launch_bounds__(256) scan_pass3()
{
    const int chunk = blockIdx.x + 1;
    const int bh    = blockIdx.y;
    const int dir   = blockIdx.z;
    const int p  = threadIdx.x & 63;
    const int tg = threadIdx.x >> 6;
    const int b = bh >> 4;
    const int h = bh & 15;

    __shared__ float Ss[64][68];
    __shared__ float Cs[2][4][64];
    __shared__ float cps[2][4];

    const float* st = g_state[dir][bh][chunk];
    for (int i = threadIdx.x; i < 4096; i += 256)
        Ss[i >> 6][i & 63] = st[i];

    const float* xbc = g_xbc[dir];
    float* yout = g_y[dir];

    auto load_group = [&](int gi, int buf) {
        const int g = chunk * LCHUNK + 4 * gi + tg;
        const int t = dir ? (SEQLEN - 1 - g) : g;
        const int row = (b << 10) + t;
        Cs[buf][tg][p] = xbc[(size_t)row * CD + DI + DS + p];
        if (p == 0) cps[buf][tg] = g_cpv[dir][bh][g];
    };

    load_group(0, 0);

    for (int gi = 0; gi < LCHUNK / 4; gi++) {
        const int buf = gi & 1;
        __syncthreads();
        if (gi + 1 < LCHUNK / 4) load_group(gi + 1, buf ^ 1);

        const int g = chunk * LCHUNK + 4 * gi + tg;
        const int t = dir ? (SEQLEN - 1 - g) : g;
        const int row = (b << 10) + t;

        float a0 = 0.f, a1 = 0.f, a2 = 0.f, a3 = 0.f;
#pragma unroll
        for (int nn = 0; nn < 64; nn += 4) {
            const float4 sv = *(const float4*)&Ss[p][nn];
            const float4 cv = *(const float4*)&Cs[buf][tg][nn];
            a0 = fmaf(sv.x, cv.x, a0);
            a1 = fmaf(sv.y, cv.y, a1);
            a2 = fmaf(sv.z, cv.z, a2);
            a3 = fmaf(sv.w, cv.w, a3);
        }
        yout[(size_t)row * DI + h * 64 + p] += cps[buf][tg] * ((a0 + a1) + (a2 + a3));
    }
}

// ---------------- block reduce helper ----------------
__device__ __forceinline__ float block_reduce_sum_256(float v, float* red)
{
#pragma unroll
    for (int o = 16; o > 0; o >>= 1) v += __shfl_xor_sync(0xffffffffu, v, o);
    if ((threadIdx.x & 31) == 0) red[threadIdx.x >> 5] = v;
    __syncthreads();
    float total = 0.f;
#pragma unroll
    for (int i = 0; i < 8; i++) total += red[i];
    return total;
}

// =====================================================================
// gated RMSNorm over D_INNER; emits fp16 hi/lo directly into GEMM A bufs.
// =====================================================================
__global__ void __launch_bounds__(256) gate_norm_kernel(const float* __restrict__ gnorm_w, int layer)
{
    const int row = blockIdx.x;
    const int dir = blockIdx.y;
    const float* y = g_y[dir] + (size_t)row * DI;
    const float* z = g_zx[dir] + (size_t)row * DIP;
    const float* gwp = gnorm_w + (size_t)(2 * layer + dir) * DI;
    const int e0 = threadIdx.x * 4;

    __shared__ float red[8];
    const float4 yv = *(const float4*)(y + e0);
    const float4 zv = *(const float4*)(z + e0);
    float v[4];
    v[0] = yv.x * (zv.x / (1.f + expf(-zv.x)));
    v[1] = yv.y * (zv.y / (1.f + expf(-zv.y)));
    v[2] = yv.z * (zv.z / (1.f + expf(-zv.z)));
    v[3] = yv.w * (zv.w / (1.f + expf(-zv.w)));
    float ss = fmaf(v[0], v[0], fmaf(v[1], v[1], fmaf(v[2], v[2], v[3] * v[3])));

    const float total = block_reduce_sum_256(ss, red);
    const float scale = rsqrtf(total * (1.f / (float)DI) + 1e-5f);

    const float4 gv = *(const float4*)(gwp + e0);
    float o[4] = { v[0] * scale * gv.x, v[1] * scale * gv.y,
                   v[2] * scale * gv.z, v[3] * scale * gv.w };

    __half hb[4], lb[4];
#pragma unroll
    for (int j = 0; j < 4; j++) {
        hb[j] = __float2half_rn(o[j]);
        lb[j] = __float2half_rn(o[j] - __half2float(hb[j]));
    }
    const size_t off = (size_t)dir * BL * DI + (size_t)row * DI + e0;
    *(__half2*)(g_ah + off)     = __half2{hb[0], hb[1]};
    *(__half2*)(g_ah + off + 2) = __half2{hb[2], hb[3]};
    *(__half2*)(g_al + off)     = __half2{lb[0], lb[1]};
    *(__half2*)(g_al + off + 2) = __half2{lb[2], lb[3]};
}

// =====================================================================
// residual RMSNorm over D_MODEL (sums both outproj split-K halves);
// emits fp32 hout AND fp16 hi/lo (next layer's in_proj A).
// =====================================================================
__global__ void __launch_bounds__(256) resid_norm_kernel(
    const float* __restrict__ hin, const float* __restrict__ nw, float* __restrict__ hout)
{
    const int row = blockIdx.x;
    const int tid = threadIdx.x;
    __shared__ float red[8];

    const size_t base = (size_t)row * DM;
    const float v0 = hin[base + tid]       + g_tmp[0][base + tid]       + g_tmp[1][base + tid];
    const float v1 = hin[base + tid + 256] + g_tmp[0][base + tid + 256] + g_tmp[1][base + tid + 256];
    const float total = block_reduce_sum_256(v0 * v0 + v1 * v1, red);
    const float scale = rsqrtf(total * (1.f / (float)DM) + 1.1920929e-07f);

    const float o0 = v0 * scale * nw[tid];
    const float o1 = v1 * scale * nw[tid + 256];
    hout[base + tid]       = o0;
    hout[base + tid + 256] = o1;

    const __half h0 = __float2half_rn(o0);
    const __half h1 = __float2half_rn(o1);
    g_ah[base + tid]       = h0;
    g_ah[base + tid + 256] = h1;
    g_al[base + tid]       = __float2half_rn(o0 - __half2float(h0));
    g_al[base + tid + 256] = __float2half_rn(o1 - __half2float(h1));
}

// =====================================================================
// Host launcher
// =====================================================================
extern "C" void kernel_launch(void* const* d_in, const int* in_sizes, int n_in,
                              void* d_out, int out_size)
{
    (void)in_sizes; (void)n_in; (void)out_size;
    const float* x    = (const float*)d_in[0];
    const float* Wi   = (const float*)d_in[1];
    const float* Wc   = (const float*)d_in[2];
    const float* bc   = (const float*)d_in[3];
    const float* dtb  = (const float*)d_in[4];
    const float* Alog = (const float*)d_in[5];
    const float* Dsk  = (const float*)d_in[6];
    const float* gw   = (const float*)d_in[7];
    const float* Wm   = (const float*)d_in[8];
    const float* nw   = (const float*)d_in[9];
    const float* Wo   = (const float*)d_in[10];
    float* out = (float*)d_out;

    cudaFuncSetAttribute(gemm_tc, cudaFuncAttributeMaxDynamicSharedMemorySize, GEMM_SMEM);

    float *zx0, *tmp, *hbuf;
    __half *ah, *al, *ch, *cl, *wih, *wmh, *woh;
    cudaGetSymbolAddress((void**)&zx0,  g_zx);
    cudaGetSymbolAddress((void**)&tmp,  g_tmp);
    cudaGetSymbolAddress((void**)&hbuf, g_h);
    cudaGetSymbolAddress((void**)&ah,   g_ah);
    cudaGetSymbolAddress((void**)&al,   g_al);
    cudaGetSymbolAddress((void**)&ch,   g_ch);
    cudaGetSymbolAddress((void**)&cl,   g_cl);
    cudaGetSymbolAddress((void**)&wih,  g_wi_h);
    cudaGetSymbolAddress((void**)&wmh,  g_wm_h);
    cudaGetSymbolAddress((void**)&woh,  g_wo_h);

    // ---- convert all weights to fp16 hi (batched over z) ----
    convert_w<<<dim3((DIPP * DM / 4 + 255) / 256, 1, 4), 256>>>(
        Wi, wih, DIP, DM, DIPP * DM / 4, (size_t)DIP * DM, (size_t)DIPP * DM);
    convert_w<<<dim3((DM * DI / 4 + 255) / 256, 1, 4), 256>>>(
        Wm, wmh, DM, DI, DM * DI / 4, (size_t)DM * DI, (size_t)DM * DI);
    convert_w<<<dim3((DM * DI / 4 + 255) / 256, 1, 1), 256>>>(
        Wo, woh, DM, DI, DM * DI / 4, 0, 0);

    for (int l = 0; l < NLAYERS; l++) {
        const float* hin = (l == 0) ? x : hbuf;
        float* hout = (l == NLAYERS - 1) ? out : hbuf;

        // in_proj A: layer 0 converts x; layer >0 uses resid_norm's fp16 output
        if (l == 0)
            convert_a<<<(BL * DM / 4 + 255) / 256, 256>>>(hin, ah, al, BL * DM / 4);
        gemm_tc<<<dim3(DIPP / 256, BL / 128, 2), 256, GEMM_SMEM>>>(
            ah, al, wih + (size_t)(2 * l) * DIPP * DM,
            zx0, nullptr, nullptr,
            DIP, DM, DM, DM, DIP,
            0, (size_t)DIPP * DM, (size_t)BL * DIP, 0);

        conv_dt_kernel<<<dim3(CD / 128, BL / CONV_TT, 2), 128>>>(Wc, bc, dtb, Alog, l);
        scan_pass1<<<dim3(NCHUNK, 64, 2), 64>>>(Dsk, l);
        scan_pass2<<<128, 256>>>();
        scan_pass3<<<dim3(NCHUNK - 1, 64, 2), 256>>>();
        gate_norm_kernel<<<dim3(BL, 2), 256>>>(gw, l);   // emits fp16 into ah/al

        // mout, both dirs in one launch; fp16 hi/lo epilogue into ch/cl
        gemm_tc<<<dim3(DM / 256, BL / 128, 2), 256, GEMM_SMEM>>>(
            ah, al, wmh + (size_t)(2 * l) * DM * DI,
            nullptr, ch, cl,
            DM, DI, DI, DI, DI,
            (size_t)BL * DI, (size_t)DM * DI, (size_t)DM, 1);

        // outproj: split-K over z (K halves of 512), fp32 halves into g_tmp
        gemm_tc<<<dim3(DM / 256, BL / 128, 2), 256, GEMM_SMEM>>>(
            ch, cl, woh,
            tmp, nullptr, nullptr,
            DM, DM /*K=512*/, DI, DI, DM,
            (size_t)DM, (size_t)DM, (size_t)BL * DM, 0);

        resid_norm_kernel<<<BL, 256>>>(hin, nw + (size_t)l * DM, hout);
    }
}